// round 12
// baseline (speedup 1.0000x reference)
#include <cuda_runtime.h>
#include <cuda_fp16.h>
#include <mma.h>
#include <cstdint>

using namespace nvcuda;

#define N_NODES_MAX 100000
#define E_MAX       3200000
#define HID   52
#define HID2  104
#define NL    3
#define ROWH  64    // halves per feature row (128 B, line-aligned)
#define TPN   8     // threads per row (8 x uint4)
#define BSTR  96    // bucket slots per node

// Scratch (zero-initialized). Row index n = sentinel, never written -> stays 0.
// Cols 52-63 of every row are never written -> stay 0.
__device__ __half g_hin[(N_NODES_MAX + 64) * ROWH];
__device__ __half g_h[NL][(N_NODES_MAX + 64) * ROWH];
__device__ __half g_w1h[NL * 64 * 112];              // [l][k 64(pad52)][j 112(pad104)]
__device__ __half g_w2h[NL * 112 * 64];              // [l][j 112(pad104)][i 64(pad52)]
__device__ __half g_lwh[208 * 64];                   // [k 208][i 64(pad52)]
__device__ int    g_deg[N_NODES_MAX];
__device__ alignas(16) int g_csrc[N_NODES_MAX * BSTR];

__device__ __forceinline__ uint32_t pack_half2(float a, float b)
{
    __half2 h = __floats2half2_rn(a, b);
    return *(uint32_t*)&h;
}

// ---------------------------------------------------------------------------
// prep: zero degrees + x -> fp16 rows of 64 halves (cols 52-63 = 0; sentinel 0)
// ---------------------------------------------------------------------------
__global__ void prep_kernel(const float* __restrict__ x, int n)
{
    int t = blockIdx.x * blockDim.x + threadIdx.x;
    if (t < n) g_deg[t] = 0;
    if (t >= (n + 1) * TPN) return;
    int node = t >> 3;
    int c = t & 7;
    uint4 u = make_uint4(0u, 0u, 0u, 0u);
    if (node < n) {
        const float* base = x + (size_t)node * HID + 8 * c;
        if (c < 6) {
            float4 a = __ldg(&((const float4*)base)[0]);
            float4 b = __ldg(&((const float4*)base)[1]);
            u.x = pack_half2(a.x, a.y); u.y = pack_half2(a.z, a.w);
            u.z = pack_half2(b.x, b.y); u.w = pack_half2(b.z, b.w);
        } else if (c == 6) {
            float4 a = __ldg(&((const float4*)base)[0]);
            u.x = pack_half2(a.x, a.y); u.y = pack_half2(a.z, a.w);
        }
    }
    ((uint4*)g_hin)[(size_t)node * TPN + c] = u;
}

__global__ void prep_weights_kernel(const float* __restrict__ w1,
                                    const float* __restrict__ w2,
                                    const float* __restrict__ lw)
{
    int idx = blockIdx.x * blockDim.x + threadIdx.x;
    const int n1 = NL * HID * HID2;
    const int n2 = NL * HID2 * HID;
    const int n3 = 4 * HID * HID;
    if (idx < n1) {
        int l = idx / (HID * HID2), r = idx % (HID * HID2);
        int k = r / HID2, j = r % HID2;
        g_w1h[l * 64 * 112 + k * 112 + j] = __float2half(w1[idx]);
    } else if (idx < n1 + n2) {
        int i2 = idx - n1;
        int l = i2 / (HID2 * HID), r = i2 % (HID2 * HID);
        int j = r / HID, i = r % HID;
        g_w2h[l * 112 * 64 + j * 64 + i] = __float2half(w2[i2]);
    } else if (idx < n1 + n2 + n3) {
        int i3 = idx - n1 - n2;
        int k = i3 / HID, i = i3 % HID;
        g_lwh[k * 64 + i] = __float2half(lw[i3]);
    }
}

// ---------------------------------------------------------------------------
// Bucket CSR build: single pass + pad fill
// ---------------------------------------------------------------------------
__global__ void place_kernel(const int* __restrict__ ei, int E)
{
    int t = blockIdx.x * blockDim.x + threadIdx.x;
    int E4 = E >> 2;
    if (t < E4) {
        int4 s = __ldg(&((const int4*)ei)[t]);
        int4 d = __ldg(&((const int4*)(ei + E))[t]);
        int p;
        p = atomicAdd(&g_deg[d.x], 1); if (p < BSTR) g_csrc[d.x * BSTR + p] = s.x;
        p = atomicAdd(&g_deg[d.y], 1); if (p < BSTR) g_csrc[d.y * BSTR + p] = s.y;
        p = atomicAdd(&g_deg[d.z], 1); if (p < BSTR) g_csrc[d.z * BSTR + p] = s.z;
        p = atomicAdd(&g_deg[d.w], 1); if (p < BSTR) g_csrc[d.w * BSTR + p] = s.w;
    } else {
        int e = (E4 << 2) + (t - E4);
        if (e < E) {
            int src = __ldg(&ei[e]);
            int dst = __ldg(&ei[E + e]);
            int p = atomicAdd(&g_deg[dst], 1);
            if (p < BSTR) g_csrc[dst * BSTR + p] = src;
        }
    }
}

__global__ void fillpad_kernel(int n)
{
    int i = blockIdx.x * blockDim.x + threadIdx.x;
    if (i >= n) return;
    int d = g_deg[i];
    if (d > BSTR) d = BSTR;
    int dp = (d + 7) & ~7;
    int base = i * BSTR;
    for (int k = d; k < dp; k++) g_csrc[base + k] = n;
}

// ---------------------------------------------------------------------------
// FUSED aggregate + MLP: 512 threads, 64 nodes per block.
// Phase A: 8 thr/node gather into sZ (smem). Phase B: WMMA 2-layer MLP.
// smem: sZ 8192 | sW1 14336 | sW2 14336 | sY 14336 | scr 16384 | b1 448 | b2 256
// ---------------------------------------------------------------------------
#define FUSE_SMEM (8192 + 14336 + 14336 + 14336 + 16384 + 448 + 256)

__global__ void __launch_bounds__(512, 2) layer_fused_kernel(
        const float* __restrict__ eps,
        const float* __restrict__ b1, const float* __restrict__ b2,
        int l, int n)
{
    extern __shared__ __align__(16) char smem[];
    __half* sZ  = (__half*)(smem);
    __half* sW1 = (__half*)(smem + 8192);
    __half* sW2 = (__half*)(smem + 22528);
    __half* sY  = (__half*)(smem + 36864);
    float*  scr = (float*)(smem + 51200);
    float*  sB1 = (float*)(smem + 67584);
    float*  sB2 = (float*)(smem + 68032);

    int t = threadIdx.x;
    int node0 = blockIdx.x * 64;

    // stage weights + biases (L2 hits; overlaps little, cheap)
    const uint4* w1g = (const uint4*)(g_w1h + (size_t)l * 64 * 112);
    for (int i = t; i < 896; i += 512) ((uint4*)sW1)[i] = __ldg(&w1g[i]);
    const uint4* w2g = (const uint4*)(g_w2h + (size_t)l * 112 * 64);
    for (int i = t; i < 896; i += 512) ((uint4*)sW2)[i] = __ldg(&w2g[i]);
    if (t < 112) sB1[t] = (t < HID2) ? __ldg(&b1[l * HID2 + t]) : 0.f;
    if (t >= 128 && t < 192) {
        int i = t - 128;
        sB2[i] = (i < HID) ? __ldg(&b2[l * HID + i]) : 0.f;
    }

    // ---- Phase A: aggregate 64 nodes into sZ ----
    {
        int nl_ = t >> 3;          // local node 0..63
        int c   = t & 7;
        int node = node0 + nl_;
        uint4 o = make_uint4(0u, 0u, 0u, 0u);
        if (node < n) {
            const uint4* __restrict__ h16 =
                (const uint4*)((l == 0) ? g_hin : g_h[l - 1]);
            float s = 1.0f + __ldg(&eps[l]);
            uint4 u = __ldg(&h16[(size_t)node * TPN + c]);
            float2 p0 = __half22float2(*(__half2*)&u.x);
            float2 p1 = __half22float2(*(__half2*)&u.y);
            float2 p2 = __half22float2(*(__half2*)&u.z);
            float2 p3 = __half22float2(*(__half2*)&u.w);
            float a0 = s * p0.x, a1 = s * p0.y, a2 = s * p1.x, a3 = s * p1.y;
            float a4 = s * p2.x, a5 = s * p2.y, a6 = s * p3.x, a7 = s * p3.y;

            int d = g_deg[node];
            if (d > BSTR) d = BSTR;
            int iters = (d + 7) >> 3;
            const int4* cs4 = (const int4*)(g_csrc + node * BSTR);

            for (int it = 0; it < iters; it++) {
                int4 i0 = __ldg(&cs4[2 * it]);
                int4 i1 = __ldg(&cs4[2 * it + 1]);
                uint4 u0 = __ldg(&h16[(size_t)i0.x * TPN + c]);
                uint4 u1 = __ldg(&h16[(size_t)i0.y * TPN + c]);
                uint4 u2 = __ldg(&h16[(size_t)i0.z * TPN + c]);
                uint4 u3 = __ldg(&h16[(size_t)i0.w * TPN + c]);
                uint4 u4 = __ldg(&h16[(size_t)i1.x * TPN + c]);
                uint4 u5 = __ldg(&h16[(size_t)i1.y * TPN + c]);
                uint4 u6 = __ldg(&h16[(size_t)i1.z * TPN + c]);
                uint4 u7 = __ldg(&h16[(size_t)i1.w * TPN + c]);
#define ACC(uu) { \
                float2 q0 = __half22float2(*(__half2*)&uu.x); \
                float2 q1 = __half22float2(*(__half2*)&uu.y); \
                float2 q2 = __half22float2(*(__half2*)&uu.z); \
                float2 q3 = __half22float2(*(__half2*)&uu.w); \
                a0 += q0.x; a1 += q0.y; a2 += q1.x; a3 += q1.y; \
                a4 += q2.x; a5 += q2.y; a6 += q3.x; a7 += q3.y; }
                ACC(u0); ACC(u1); ACC(u2); ACC(u3);
                ACC(u4); ACC(u5); ACC(u6); ACC(u7);
#undef ACC
            }
            o.x = pack_half2(a0, a1);
            o.y = pack_half2(a2, a3);
            o.z = pack_half2(a4, a5);
            o.w = pack_half2(a6, a7);
        }
        ((uint4*)sZ)[(size_t)nl_ * TPN + c] = o;
    }
    __syncthreads();

    // ---- Phase B: WMMA MLP ----
    int wid = t >> 5, lane = t & 31;
    float* myscr = scr + wid * 256;

    wmma::fragment<wmma::matrix_a, 16, 16, 16, __half, wmma::row_major> fa;
    wmma::fragment<wmma::matrix_b, 16, 16, 16, __half, wmma::row_major> fb;
    wmma::fragment<wmma::accumulator, 16, 16, 16, float> fc;

    // GEMM1: 28 jobs over 16 warps
    for (int job = wid; job < 28; job += 16) {
        int mt = job & 3;
        int nt = job >> 2;
        wmma::fill_fragment(fc, 0.0f);
#pragma unroll
        for (int kk = 0; kk < 4; kk++) {
            wmma::load_matrix_sync(fa, sZ + (mt * 16) * 64 + kk * 16, 64);
            wmma::load_matrix_sync(fb, sW1 + (kk * 16) * 112 + nt * 16, 112);
            wmma::mma_sync(fc, fa, fb, fc);
        }
        wmma::store_matrix_sync(myscr, fc, 16, wmma::mem_row_major);
        __syncwarp();
        for (int e = lane; e < 256; e += 32) {
            int r = e >> 4, cc = e & 15;
            int gc = nt * 16 + cc;
            float v = fmaxf(myscr[e] + sB1[gc], 0.0f);
            sY[(mt * 16 + r) * 112 + gc] = __float2half(v);
        }
        __syncwarp();
    }
    __syncthreads();

    // GEMM2: 16 jobs over 16 warps
    __half* hout = g_h[l];
    for (int job = wid; job < 16; job += 16) {
        int mt = job & 3;
        int nt = job >> 2;
        wmma::fill_fragment(fc, 0.0f);
#pragma unroll
        for (int kk = 0; kk < 7; kk++) {
            wmma::load_matrix_sync(fa, sY + (mt * 16) * 112 + kk * 16, 112);
            wmma::load_matrix_sync(fb, sW2 + (kk * 16) * 64 + nt * 16, 64);
            wmma::mma_sync(fc, fa, fb, fc);
        }
        wmma::store_matrix_sync(myscr, fc, 16, wmma::mem_row_major);
        __syncwarp();
        for (int e = lane; e < 256; e += 32) {
            int r = e >> 4, cc = e & 15;
            int gr = node0 + mt * 16 + r;
            int gc = nt * 16 + cc;
            if (gc < HID && gr < n) {
                float v = fmaxf(myscr[e] + sB2[gc], 0.0f);
                hout[(size_t)gr * ROWH + gc] = __float2half(v);
            }
        }
        __syncwarp();
    }
}

// ---------------------------------------------------------------------------
// WMMA final (h row stride 64 halves)
// ---------------------------------------------------------------------------
#define FIN_SMEM 61696

__global__ void __launch_bounds__(256) final_wmma_kernel(
        const float* __restrict__ lb, float* __restrict__ out, int n)
{
    extern __shared__ __align__(16) char smem[];
    __half* sH  = (__half*)(smem);
    __half* sW  = (__half*)(smem + 26624);
    float*  scr = (float*)(smem + 53248);
    float*  sLB = (float*)(smem + 61440);

    int t = threadIdx.x;
    int node0 = blockIdx.x * 64;

    {
        int node = t & 63, seg = t >> 6;
        const __half* src = ((seg == 0) ? g_hin : g_h[seg - 1])
                            + (size_t)(node0 + node) * ROWH;
        const uint2* s2 = (const uint2*)src;
        uint2* d2 = (uint2*)(sH + node * 208 + seg * HID);
#pragma unroll
        for (int i = 0; i < 13; i++) d2[i] = __ldg(&s2[i]);
    }
    for (int i = t; i < 1664; i += 256)
        ((uint4*)sW)[i] = __ldg(&((const uint4*)g_lwh)[i]);
    if (t < 64) sLB[t] = (t < HID) ? __ldg(&lb[t]) : 0.f;
    __syncthreads();

    int wid = t >> 5, lane = t & 31;
    float* myscr = scr + wid * 256;

    wmma::fragment<wmma::matrix_a, 16, 16, 16, __half, wmma::row_major> fa;
    wmma::fragment<wmma::matrix_b, 16, 16, 16, __half, wmma::row_major> fb;
    wmma::fragment<wmma::accumulator, 16, 16, 16, float> fc;

    for (int job = wid; job < 16; job += 8) {
        int mt = job & 3;
        int nt = job >> 2;
        wmma::fill_fragment(fc, 0.0f);
#pragma unroll
        for (int kk = 0; kk < 13; kk++) {
            wmma::load_matrix_sync(fa, sH + (mt * 16) * 208 + kk * 16, 208);
            wmma::load_matrix_sync(fb, sW + (kk * 16) * 64 + nt * 16, 64);
            wmma::mma_sync(fc, fa, fb, fc);
        }
        wmma::store_matrix_sync(myscr, fc, 16, wmma::mem_row_major);
        __syncwarp();
        for (int e = lane; e < 256; e += 32) {
            int r = e >> 4, cc = e & 15;
            int gr = node0 + mt * 16 + r;
            int gc = nt * 16 + cc;
            if (gc < HID && gr < n)
                out[(size_t)gr * HID + gc] = myscr[e] + sLB[gc];
        }
        __syncwarp();
    }
}

// ---------------------------------------------------------------------------
extern "C" void kernel_launch(void* const* d_in, const int* in_sizes, int n_in,
                              void* d_out, int out_size)
{
    const float* x    = (const float*)d_in[0];
    const int*   ei   = (const int*)  d_in[1];
    const float* w1   = (const float*)d_in[2];
    const float* b1   = (const float*)d_in[3];
    const float* w2   = (const float*)d_in[4];
    const float* b2   = (const float*)d_in[5];
    const float* eps  = (const float*)d_in[6];
    const float* lw   = (const float*)d_in[7];
    const float* lb   = (const float*)d_in[8];
    float* out = (float*)d_out;

    int n = in_sizes[0] / HID;
    int E = in_sizes[1] / 2;

    cudaFuncSetAttribute(layer_fused_kernel,
                         cudaFuncAttributeMaxDynamicSharedMemorySize, FUSE_SMEM);
    cudaFuncSetAttribute(final_wmma_kernel,
                         cudaFuncAttributeMaxDynamicSharedMemorySize, FIN_SMEM);

    int nodeBlocks = (n + 255) / 256;
    int prepBlocks = ((n + 1) * TPN + 255) / 256;
    int wBlocks    = (NL * HID * HID2 * 2 + 4 * HID * HID + 255) / 256;
    int plcBlocks  = ((E >> 2) + (E & 3) + 255) / 256;
    int tcBlocks   = (n + 63) / 64;

    prep_kernel<<<prepBlocks, 256>>>(x, n);
    prep_weights_kernel<<<wBlocks, 256>>>(w1, w2, lw);
    place_kernel<<<plcBlocks, 256>>>(ei, E);
    fillpad_kernel<<<nodeBlocks, 256>>>(n);

    for (int l = 0; l < NL; l++)
        layer_fused_kernel<<<tcBlocks, 512, FUSE_SMEM>>>(eps, b1, b2, l, n);

    final_wmma_kernel<<<tcBlocks, 256, FIN_SMEM>>>(lb, out, n);
}

// round 13
// speedup vs baseline: 1.0099x; 1.0099x over previous
#include <cuda_runtime.h>
#include <cuda_fp16.h>
#include <mma.h>
#include <cstdint>

using namespace nvcuda;

#define N_NODES_MAX 100000
#define E_MAX       3200000
#define HID   52
#define HID2  104
#define NL    3
#define ROWH  64    // halves per feature row (128 B, line-aligned)
#define TPN   8     // threads per row (8 x uint4)
#define BSTR  96    // bucket slots per node

// Scratch (zero-initialized). Row index n = sentinel, never written -> stays 0.
// Cols 52-63 of every row are never written -> stay 0.
__device__ __half g_hin[(N_NODES_MAX + 64) * ROWH];
__device__ __half g_h[NL][(N_NODES_MAX + 64) * ROWH];
__device__ __half g_w1h[NL * 64 * 112];              // [l][k 64(pad52)][j 112(pad104)]
__device__ __half g_w2h[NL * 112 * 64];              // [l][j 112(pad104)][i 64(pad52)]
__device__ __half g_lwh[208 * 64];                   // [k 208][i 64(pad52)]
__device__ int    g_deg[N_NODES_MAX];
__device__ alignas(16) int g_csrc[N_NODES_MAX * BSTR];

__device__ __forceinline__ uint32_t pack_half2(float a, float b)
{
    __half2 h = __floats2half2_rn(a, b);
    return *(uint32_t*)&h;
}

// ---------------------------------------------------------------------------
// prep: zero degrees + x -> fp16 rows of 64 halves (cols 52-63 = 0; sentinel 0)
// ---------------------------------------------------------------------------
__global__ void prep_kernel(const float* __restrict__ x, int n)
{
    int t = blockIdx.x * blockDim.x + threadIdx.x;
    if (t < n) g_deg[t] = 0;
    if (t >= (n + 1) * TPN) return;
    int node = t >> 3;
    int c = t & 7;
    uint4 u = make_uint4(0u, 0u, 0u, 0u);
    if (node < n) {
        const float* base = x + (size_t)node * HID + 8 * c;
        if (c < 6) {
            float4 a = __ldg(&((const float4*)base)[0]);
            float4 b = __ldg(&((const float4*)base)[1]);
            u.x = pack_half2(a.x, a.y); u.y = pack_half2(a.z, a.w);
            u.z = pack_half2(b.x, b.y); u.w = pack_half2(b.z, b.w);
        } else if (c == 6) {
            float4 a = __ldg(&((const float4*)base)[0]);
            u.x = pack_half2(a.x, a.y); u.y = pack_half2(a.z, a.w);
        }
    }
    ((uint4*)g_hin)[(size_t)node * TPN + c] = u;
}

__global__ void prep_weights_kernel(const float* __restrict__ w1,
                                    const float* __restrict__ w2,
                                    const float* __restrict__ lw)
{
    int idx = blockIdx.x * blockDim.x + threadIdx.x;
    const int n1 = NL * HID * HID2;
    const int n2 = NL * HID2 * HID;
    const int n3 = 4 * HID * HID;
    if (idx < n1) {
        int l = idx / (HID * HID2), r = idx % (HID * HID2);
        int k = r / HID2, j = r % HID2;
        g_w1h[l * 64 * 112 + k * 112 + j] = __float2half(w1[idx]);
    } else if (idx < n1 + n2) {
        int i2 = idx - n1;
        int l = i2 / (HID2 * HID), r = i2 % (HID2 * HID);
        int j = r / HID, i = r % HID;
        g_w2h[l * 112 * 64 + j * 64 + i] = __float2half(w2[i2]);
    } else if (idx < n1 + n2 + n3) {
        int i3 = idx - n1 - n2;
        int k = i3 / HID, i = i3 % HID;
        g_lwh[k * 64 + i] = __float2half(lw[i3]);
    }
}

// ---------------------------------------------------------------------------
// Bucket CSR build: 8 edges/thread single pass + pad fill
// ---------------------------------------------------------------------------
__global__ void place_kernel(const int* __restrict__ ei, int E)
{
    int t = blockIdx.x * blockDim.x + threadIdx.x;
    int E8 = E >> 3;
    if (t < E8) {
        const int4* s4 = (const int4*)ei;
        const int4* d4 = (const int4*)(ei + E);
        int4 s0 = __ldg(&s4[2 * t]);
        int4 s1 = __ldg(&s4[2 * t + 1]);
        int4 d0 = __ldg(&d4[2 * t]);
        int4 d1 = __ldg(&d4[2 * t + 1]);
        int p;
        p = atomicAdd(&g_deg[d0.x], 1); if (p < BSTR) g_csrc[d0.x * BSTR + p] = s0.x;
        p = atomicAdd(&g_deg[d0.y], 1); if (p < BSTR) g_csrc[d0.y * BSTR + p] = s0.y;
        p = atomicAdd(&g_deg[d0.z], 1); if (p < BSTR) g_csrc[d0.z * BSTR + p] = s0.z;
        p = atomicAdd(&g_deg[d0.w], 1); if (p < BSTR) g_csrc[d0.w * BSTR + p] = s0.w;
        p = atomicAdd(&g_deg[d1.x], 1); if (p < BSTR) g_csrc[d1.x * BSTR + p] = s1.x;
        p = atomicAdd(&g_deg[d1.y], 1); if (p < BSTR) g_csrc[d1.y * BSTR + p] = s1.y;
        p = atomicAdd(&g_deg[d1.z], 1); if (p < BSTR) g_csrc[d1.z * BSTR + p] = s1.z;
        p = atomicAdd(&g_deg[d1.w], 1); if (p < BSTR) g_csrc[d1.w * BSTR + p] = s1.w;
    } else {
        int e = (E8 << 3) + (t - E8);
        if (e < E) {
            int src = __ldg(&ei[e]);
            int dst = __ldg(&ei[E + e]);
            int p = atomicAdd(&g_deg[dst], 1);
            if (p < BSTR) g_csrc[dst * BSTR + p] = src;
        }
    }
}

__global__ void fillpad_kernel(int n)
{
    int i = blockIdx.x * blockDim.x + threadIdx.x;
    if (i >= n) return;
    int d = g_deg[i];
    if (d > BSTR) d = BSTR;
    int dp = (d + 7) & ~7;
    int base = i * BSTR;
    for (int k = d; k < dp; k++) g_csrc[base + k] = n;
}

// ---------------------------------------------------------------------------
// FUSED aggregate + MLP, with software-pipelined index loads in phase A.
// ---------------------------------------------------------------------------
#define FUSE_SMEM (8192 + 14336 + 14336 + 14336 + 16384 + 448 + 256)

__global__ void __launch_bounds__(512, 2) layer_fused_kernel(
        const float* __restrict__ eps,
        const float* __restrict__ b1, const float* __restrict__ b2,
        int l, int n)
{
    extern __shared__ __align__(16) char smem[];
    __half* sZ  = (__half*)(smem);
    __half* sW1 = (__half*)(smem + 8192);
    __half* sW2 = (__half*)(smem + 22528);
    __half* sY  = (__half*)(smem + 36864);
    float*  scr = (float*)(smem + 51200);
    float*  sB1 = (float*)(smem + 67584);
    float*  sB2 = (float*)(smem + 68032);

    int t = threadIdx.x;
    int node0 = blockIdx.x * 64;

    const uint4* w1g = (const uint4*)(g_w1h + (size_t)l * 64 * 112);
    for (int i = t; i < 896; i += 512) ((uint4*)sW1)[i] = __ldg(&w1g[i]);
    const uint4* w2g = (const uint4*)(g_w2h + (size_t)l * 112 * 64);
    for (int i = t; i < 896; i += 512) ((uint4*)sW2)[i] = __ldg(&w2g[i]);
    if (t < 112) sB1[t] = (t < HID2) ? __ldg(&b1[l * HID2 + t]) : 0.f;
    if (t >= 128 && t < 192) {
        int i = t - 128;
        sB2[i] = (i < HID) ? __ldg(&b2[l * HID + i]) : 0.f;
    }

    // ---- Phase A: aggregate 64 nodes into sZ (index loads pipelined) ----
    {
        int nl_ = t >> 3;          // local node 0..63
        int c   = t & 7;
        int node = node0 + nl_;
        uint4 o = make_uint4(0u, 0u, 0u, 0u);
        if (node < n) {
            const uint4* __restrict__ h16 =
                (const uint4*)((l == 0) ? g_hin : g_h[l - 1]);
            float s = 1.0f + __ldg(&eps[l]);
            uint4 u = __ldg(&h16[(size_t)node * TPN + c]);
            float2 p0 = __half22float2(*(__half2*)&u.x);
            float2 p1 = __half22float2(*(__half2*)&u.y);
            float2 p2 = __half22float2(*(__half2*)&u.z);
            float2 p3 = __half22float2(*(__half2*)&u.w);
            float a0 = s * p0.x, a1 = s * p0.y, a2 = s * p1.x, a3 = s * p1.y;
            float a4 = s * p2.x, a5 = s * p2.y, a6 = s * p3.x, a7 = s * p3.y;

            int d = g_deg[node];
            if (d > BSTR) d = BSTR;
            int iters = (d + 7) >> 3;
            const int4* cs4 = (const int4*)(g_csrc + node * BSTR);
            const int maxi = (BSTR / 4) - 2;   // clamp for prefetch over-read

            if (iters > 0) {
                int4 i0 = __ldg(&cs4[0]);
                int4 i1 = __ldg(&cs4[1]);
                for (int it = 0; it < iters; it++) {
                    // prefetch next iteration's indices (clamped; slots hold
                    // valid row ids in [0,n]; discarded on last iteration)
                    int nx = 2 * it + 2;
                    if (nx > maxi) nx = maxi;
                    int4 j0 = __ldg(&cs4[nx]);
                    int4 j1 = __ldg(&cs4[nx + 1]);

                    uint4 u0 = __ldg(&h16[(size_t)i0.x * TPN + c]);
                    uint4 u1 = __ldg(&h16[(size_t)i0.y * TPN + c]);
                    uint4 u2 = __ldg(&h16[(size_t)i0.z * TPN + c]);
                    uint4 u3 = __ldg(&h16[(size_t)i0.w * TPN + c]);
                    uint4 u4 = __ldg(&h16[(size_t)i1.x * TPN + c]);
                    uint4 u5 = __ldg(&h16[(size_t)i1.y * TPN + c]);
                    uint4 u6 = __ldg(&h16[(size_t)i1.z * TPN + c]);
                    uint4 u7 = __ldg(&h16[(size_t)i1.w * TPN + c]);
#define ACC(uu) { \
                    float2 q0 = __half22float2(*(__half2*)&uu.x); \
                    float2 q1 = __half22float2(*(__half2*)&uu.y); \
                    float2 q2 = __half22float2(*(__half2*)&uu.z); \
                    float2 q3 = __half22float2(*(__half2*)&uu.w); \
                    a0 += q0.x; a1 += q0.y; a2 += q1.x; a3 += q1.y; \
                    a4 += q2.x; a5 += q2.y; a6 += q3.x; a7 += q3.y; }
                    ACC(u0); ACC(u1); ACC(u2); ACC(u3);
                    ACC(u4); ACC(u5); ACC(u6); ACC(u7);
#undef ACC
                    i0 = j0; i1 = j1;
                }
            }
            o.x = pack_half2(a0, a1);
            o.y = pack_half2(a2, a3);
            o.z = pack_half2(a4, a5);
            o.w = pack_half2(a6, a7);
        }
        ((uint4*)sZ)[(size_t)nl_ * TPN + c] = o;
    }
    __syncthreads();

    // ---- Phase B: WMMA MLP ----
    int wid = t >> 5, lane = t & 31;
    float* myscr = scr + wid * 256;

    wmma::fragment<wmma::matrix_a, 16, 16, 16, __half, wmma::row_major> fa;
    wmma::fragment<wmma::matrix_b, 16, 16, 16, __half, wmma::row_major> fb;
    wmma::fragment<wmma::accumulator, 16, 16, 16, float> fc;

    for (int job = wid; job < 28; job += 16) {
        int mt = job & 3;
        int nt = job >> 2;
        wmma::fill_fragment(fc, 0.0f);
#pragma unroll
        for (int kk = 0; kk < 4; kk++) {
            wmma::load_matrix_sync(fa, sZ + (mt * 16) * 64 + kk * 16, 64);
            wmma::load_matrix_sync(fb, sW1 + (kk * 16) * 112 + nt * 16, 112);
            wmma::mma_sync(fc, fa, fb, fc);
        }
        wmma::store_matrix_sync(myscr, fc, 16, wmma::mem_row_major);
        __syncwarp();
        for (int e = lane; e < 256; e += 32) {
            int r = e >> 4, cc = e & 15;
            int gc = nt * 16 + cc;
            float v = fmaxf(myscr[e] + sB1[gc], 0.0f);
            sY[(mt * 16 + r) * 112 + gc] = __float2half(v);
        }
        __syncwarp();
    }
    __syncthreads();

    __half* hout = g_h[l];
    for (int job = wid; job < 16; job += 16) {
        int mt = job & 3;
        int nt = job >> 2;
        wmma::fill_fragment(fc, 0.0f);
#pragma unroll
        for (int kk = 0; kk < 7; kk++) {
            wmma::load_matrix_sync(fa, sY + (mt * 16) * 112 + kk * 16, 112);
            wmma::load_matrix_sync(fb, sW2 + (kk * 16) * 64 + nt * 16, 64);
            wmma::mma_sync(fc, fa, fb, fc);
        }
        wmma::store_matrix_sync(myscr, fc, 16, wmma::mem_row_major);
        __syncwarp();
        for (int e = lane; e < 256; e += 32) {
            int r = e >> 4, cc = e & 15;
            int gr = node0 + mt * 16 + r;
            int gc = nt * 16 + cc;
            if (gc < HID && gr < n) {
                float v = fmaxf(myscr[e] + sB2[gc], 0.0f);
                hout[(size_t)gr * ROWH + gc] = __float2half(v);
            }
        }
        __syncwarp();
    }
}

// ---------------------------------------------------------------------------
// WMMA final (h row stride 64 halves)
// ---------------------------------------------------------------------------
#define FIN_SMEM 61696

__global__ void __launch_bounds__(256) final_wmma_kernel(
        const float* __restrict__ lb, float* __restrict__ out, int n)
{
    extern __shared__ __align__(16) char smem[];
    __half* sH  = (__half*)(smem);
    __half* sW  = (__half*)(smem + 26624);
    float*  scr = (float*)(smem + 53248);
    float*  sLB = (float*)(smem + 61440);

    int t = threadIdx.x;
    int node0 = blockIdx.x * 64;

    {
        int node = t & 63, seg = t >> 6;
        const __half* src = ((seg == 0) ? g_hin : g_h[seg - 1])
                            + (size_t)(node0 + node) * ROWH;
        const uint2* s2 = (const uint2*)src;
        uint2* d2 = (uint2*)(sH + node * 208 + seg * HID);
#pragma unroll
        for (int i = 0; i < 13; i++) d2[i] = __ldg(&s2[i]);
    }
    for (int i = t; i < 1664; i += 256)
        ((uint4*)sW)[i] = __ldg(&((const uint4*)g_lwh)[i]);
    if (t < 64) sLB[t] = (t < HID) ? __ldg(&lb[t]) : 0.f;
    __syncthreads();

    int wid = t >> 5, lane = t & 31;
    float* myscr = scr + wid * 256;

    wmma::fragment<wmma::matrix_a, 16, 16, 16, __half, wmma::row_major> fa;
    wmma::fragment<wmma::matrix_b, 16, 16, 16, __half, wmma::row_major> fb;
    wmma::fragment<wmma::accumulator, 16, 16, 16, float> fc;

    for (int job = wid; job < 16; job += 8) {
        int mt = job & 3;
        int nt = job >> 2;
        wmma::fill_fragment(fc, 0.0f);
#pragma unroll
        for (int kk = 0; kk < 13; kk++) {
            wmma::load_matrix_sync(fa, sH + (mt * 16) * 208 + kk * 16, 208);
            wmma::load_matrix_sync(fb, sW + (kk * 16) * 64 + nt * 16, 64);
            wmma::mma_sync(fc, fa, fb, fc);
        }
        wmma::store_matrix_sync(myscr, fc, 16, wmma::mem_row_major);
        __syncwarp();
        for (int e = lane; e < 256; e += 32) {
            int r = e >> 4, cc = e & 15;
            int gr = node0 + mt * 16 + r;
            int gc = nt * 16 + cc;
            if (gc < HID && gr < n)
                out[(size_t)gr * HID + gc] = myscr[e] + sLB[gc];
        }
        __syncwarp();
    }
}

// ---------------------------------------------------------------------------
extern "C" void kernel_launch(void* const* d_in, const int* in_sizes, int n_in,
                              void* d_out, int out_size)
{
    const float* x    = (const float*)d_in[0];
    const int*   ei   = (const int*)  d_in[1];
    const float* w1   = (const float*)d_in[2];
    const float* b1   = (const float*)d_in[3];
    const float* w2   = (const float*)d_in[4];
    const float* b2   = (const float*)d_in[5];
    const float* eps  = (const float*)d_in[6];
    const float* lw   = (const float*)d_in[7];
    const float* lb   = (const float*)d_in[8];
    float* out = (float*)d_out;

    int n = in_sizes[0] / HID;
    int E = in_sizes[1] / 2;

    cudaFuncSetAttribute(layer_fused_kernel,
                         cudaFuncAttributeMaxDynamicSharedMemorySize, FUSE_SMEM);
    cudaFuncSetAttribute(final_wmma_kernel,
                         cudaFuncAttributeMaxDynamicSharedMemorySize, FIN_SMEM);

    int nodeBlocks = (n + 255) / 256;
    int prepBlocks = ((n + 1) * TPN + 255) / 256;
    int wBlocks    = (NL * HID * HID2 * 2 + 4 * HID * HID + 255) / 256;
    int plcBlocks  = ((E >> 3) + (E & 7) + 255) / 256;
    int tcBlocks   = (n + 63) / 64;

    prep_kernel<<<prepBlocks, 256>>>(x, n);
    prep_weights_kernel<<<wBlocks, 256>>>(w1, w2, lw);
    place_kernel<<<plcBlocks, 256>>>(ei, E);
    fillpad_kernel<<<nodeBlocks, 256>>>(n);

    for (int l = 0; l < NL; l++)
        layer_fused_kernel<<<tcBlocks, 512, FUSE_SMEM>>>(eps, b1, b2, l, n);

    final_wmma_kernel<<<tcBlocks, 256, FIN_SMEM>>>(lb, out, n);
}

// round 14
// speedup vs baseline: 1.0199x; 1.0099x over previous
#include <cuda_runtime.h>
#include <cuda_fp16.h>
#include <mma.h>
#include <cstdint>

using namespace nvcuda;

#define N_NODES_MAX 100000
#define E_MAX       3200000
#define HID   52
#define HID2  104
#define NL    3
#define ROWH  64    // halves per feature row (128 B, line-aligned)
#define TPN   8     // threads per row (8 x uint4)
#define BSTR  96    // bucket slots per node

// Scratch (zero-initialized). Row index n = sentinel, never written -> stays 0.
// Cols 52-63 of every row are never written -> stay 0.
// g_deg contract: zero at entry of every call (module-init for call 1;
// final_wmma_kernel prologue re-zeroes it for the next call).
__device__ __half g_hin[(N_NODES_MAX + 64) * ROWH];
__device__ __half g_h[NL][(N_NODES_MAX + 64) * ROWH];
__device__ __half g_w1h[NL * 64 * 112];              // [l][k 64(pad52)][j 112(pad104)]
__device__ __half g_w2h[NL * 112 * 64];              // [l][j 112(pad104)][i 64(pad52)]
__device__ __half g_lwh[208 * 64];                   // [k 208][i 64(pad52)]
__device__ int    g_deg[N_NODES_MAX];
__device__ alignas(16) int g_csrc[N_NODES_MAX * BSTR];

__device__ __forceinline__ uint32_t pack_half2(float a, float b)
{
    __half2 h = __floats2half2_rn(a, b);
    return *(uint32_t*)&h;
}

// ---------------------------------------------------------------------------
// Fused prep + place + weight-convert (disjoint thread ranges, independent).
//   [0, prepT):            x -> fp16 rows of 64 halves (+ sentinel row)
//   [prepT, prepT+placeT): bucket CSR build (8 edges/thread + remainder)
//   [.., +wT):             fp32 -> fp16 weight conversion
// ---------------------------------------------------------------------------
__global__ void build_kernel(const float* __restrict__ x,
                             const int* __restrict__ ei,
                             const float* __restrict__ w1,
                             const float* __restrict__ w2,
                             const float* __restrict__ lw,
                             int n, int E)
{
    const int prepT  = (n + 1) * TPN;
    const int E8     = E >> 3;
    const int placeT = E8 + (E & 7);
    const int n1 = NL * HID * HID2;
    const int n2 = NL * HID2 * HID;
    const int n3 = 4 * HID * HID;

    int t = blockIdx.x * blockDim.x + threadIdx.x;

    if (t < prepT) {
        int node = t >> 3;
        int c = t & 7;
        uint4 u = make_uint4(0u, 0u, 0u, 0u);
        if (node < n) {
            const float* base = x + (size_t)node * HID + 8 * c;
            if (c < 6) {
                float4 a = __ldg(&((const float4*)base)[0]);
                float4 b = __ldg(&((const float4*)base)[1]);
                u.x = pack_half2(a.x, a.y); u.y = pack_half2(a.z, a.w);
                u.z = pack_half2(b.x, b.y); u.w = pack_half2(b.z, b.w);
            } else if (c == 6) {
                float4 a = __ldg(&((const float4*)base)[0]);
                u.x = pack_half2(a.x, a.y); u.y = pack_half2(a.z, a.w);
            }
        }
        ((uint4*)g_hin)[(size_t)node * TPN + c] = u;
        return;
    }
    t -= prepT;
    if (t < placeT) {
        if (t < E8) {
            const int4* s4 = (const int4*)ei;
            const int4* d4 = (const int4*)(ei + E);
            int4 s0 = __ldg(&s4[2 * t]);
            int4 s1 = __ldg(&s4[2 * t + 1]);
            int4 d0 = __ldg(&d4[2 * t]);
            int4 d1 = __ldg(&d4[2 * t + 1]);
            int p;
            p = atomicAdd(&g_deg[d0.x], 1); if (p < BSTR) g_csrc[d0.x * BSTR + p] = s0.x;
            p = atomicAdd(&g_deg[d0.y], 1); if (p < BSTR) g_csrc[d0.y * BSTR + p] = s0.y;
            p = atomicAdd(&g_deg[d0.z], 1); if (p < BSTR) g_csrc[d0.z * BSTR + p] = s0.z;
            p = atomicAdd(&g_deg[d0.w], 1); if (p < BSTR) g_csrc[d0.w * BSTR + p] = s0.w;
            p = atomicAdd(&g_deg[d1.x], 1); if (p < BSTR) g_csrc[d1.x * BSTR + p] = s1.x;
            p = atomicAdd(&g_deg[d1.y], 1); if (p < BSTR) g_csrc[d1.y * BSTR + p] = s1.y;
            p = atomicAdd(&g_deg[d1.z], 1); if (p < BSTR) g_csrc[d1.z * BSTR + p] = s1.z;
            p = atomicAdd(&g_deg[d1.w], 1); if (p < BSTR) g_csrc[d1.w * BSTR + p] = s1.w;
        } else {
            int e = (E8 << 3) + (t - E8);
            if (e < E) {
                int src = __ldg(&ei[e]);
                int dst = __ldg(&ei[E + e]);
                int p = atomicAdd(&g_deg[dst], 1);
                if (p < BSTR) g_csrc[dst * BSTR + p] = src;
            }
        }
        return;
    }
    t -= placeT;
    if (t < n1) {
        int l = t / (HID * HID2), r = t % (HID * HID2);
        int k = r / HID2, j = r % HID2;
        g_w1h[l * 64 * 112 + k * 112 + j] = __float2half(w1[t]);
    } else if (t < n1 + n2) {
        int i2 = t - n1;
        int l = i2 / (HID2 * HID), r = i2 % (HID2 * HID);
        int j = r / HID, i = r % HID;
        g_w2h[l * 112 * 64 + j * 64 + i] = __float2half(w2[i2]);
    } else if (t < n1 + n2 + n3) {
        int i3 = t - n1 - n2;
        int k = i3 / HID, i = i3 % HID;
        g_lwh[k * 64 + i] = __float2half(lw[i3]);
    }
}

// ---------------------------------------------------------------------------
// FUSED aggregate + MLP. Pad slots masked to sentinel in-loop (no fillpad).
// ---------------------------------------------------------------------------
#define FUSE_SMEM (8192 + 14336 + 14336 + 14336 + 16384 + 448 + 256)

__global__ void __launch_bounds__(512, 2) layer_fused_kernel(
        const float* __restrict__ eps,
        const float* __restrict__ b1, const float* __restrict__ b2,
        int l, int n)
{
    extern __shared__ __align__(16) char smem[];
    __half* sZ  = (__half*)(smem);
    __half* sW1 = (__half*)(smem + 8192);
    __half* sW2 = (__half*)(smem + 22528);
    __half* sY  = (__half*)(smem + 36864);
    float*  scr = (float*)(smem + 51200);
    float*  sB1 = (float*)(smem + 67584);
    float*  sB2 = (float*)(smem + 68032);

    int t = threadIdx.x;
    int node0 = blockIdx.x * 64;

    const uint4* w1g = (const uint4*)(g_w1h + (size_t)l * 64 * 112);
    for (int i = t; i < 896; i += 512) ((uint4*)sW1)[i] = __ldg(&w1g[i]);
    const uint4* w2g = (const uint4*)(g_w2h + (size_t)l * 112 * 64);
    for (int i = t; i < 896; i += 512) ((uint4*)sW2)[i] = __ldg(&w2g[i]);
    if (t < 112) sB1[t] = (t < HID2) ? __ldg(&b1[l * HID2 + t]) : 0.f;
    if (t >= 128 && t < 192) {
        int i = t - 128;
        sB2[i] = (i < HID) ? __ldg(&b2[l * HID + i]) : 0.f;
    }

    // ---- Phase A: aggregate 64 nodes into sZ ----
    {
        int nl_ = t >> 3;          // local node 0..63
        int c   = t & 7;
        int node = node0 + nl_;
        uint4 o = make_uint4(0u, 0u, 0u, 0u);
        if (node < n) {
            const uint4* __restrict__ h16 =
                (const uint4*)((l == 0) ? g_hin : g_h[l - 1]);
            float s = 1.0f + __ldg(&eps[l]);
            uint4 u = __ldg(&h16[(size_t)node * TPN + c]);
            float2 p0 = __half22float2(*(__half2*)&u.x);
            float2 p1 = __half22float2(*(__half2*)&u.y);
            float2 p2 = __half22float2(*(__half2*)&u.z);
            float2 p3 = __half22float2(*(__half2*)&u.w);
            float a0 = s * p0.x, a1 = s * p0.y, a2 = s * p1.x, a3 = s * p1.y;
            float a4 = s * p2.x, a5 = s * p2.y, a6 = s * p3.x, a7 = s * p3.y;

            int d = g_deg[node];
            if (d > BSTR) d = BSTR;
            int iters = (d + 7) >> 3;
            const int4* cs4 = (const int4*)(g_csrc + node * BSTR);
            const int maxi = (BSTR / 4) - 2;

            if (iters > 0) {
                int4 i0 = __ldg(&cs4[0]);
                int4 i1 = __ldg(&cs4[1]);
                for (int it = 0; it < iters; it++) {
                    int nx = 2 * it + 2;
                    if (nx > maxi) nx = maxi;
                    int4 j0 = __ldg(&cs4[nx]);
                    int4 j1 = __ldg(&cs4[nx + 1]);

                    // mask pad slots (>= d) to the sentinel zero-row n
                    int sb = 8 * it;
                    int e0 = (sb + 0 < d) ? i0.x : n;
                    int e1 = (sb + 1 < d) ? i0.y : n;
                    int e2 = (sb + 2 < d) ? i0.z : n;
                    int e3 = (sb + 3 < d) ? i0.w : n;
                    int e4 = (sb + 4 < d) ? i1.x : n;
                    int e5 = (sb + 5 < d) ? i1.y : n;
                    int e6 = (sb + 6 < d) ? i1.z : n;
                    int e7 = (sb + 7 < d) ? i1.w : n;

                    uint4 u0 = __ldg(&h16[(size_t)e0 * TPN + c]);
                    uint4 u1 = __ldg(&h16[(size_t)e1 * TPN + c]);
                    uint4 u2 = __ldg(&h16[(size_t)e2 * TPN + c]);
                    uint4 u3 = __ldg(&h16[(size_t)e3 * TPN + c]);
                    uint4 u4 = __ldg(&h16[(size_t)e4 * TPN + c]);
                    uint4 u5 = __ldg(&h16[(size_t)e5 * TPN + c]);
                    uint4 u6 = __ldg(&h16[(size_t)e6 * TPN + c]);
                    uint4 u7 = __ldg(&h16[(size_t)e7 * TPN + c]);
#define ACC(uu) { \
                    float2 q0 = __half22float2(*(__half2*)&uu.x); \
                    float2 q1 = __half22float2(*(__half2*)&uu.y); \
                    float2 q2 = __half22float2(*(__half2*)&uu.z); \
                    float2 q3 = __half22float2(*(__half2*)&uu.w); \
                    a0 += q0.x; a1 += q0.y; a2 += q1.x; a3 += q1.y; \
                    a4 += q2.x; a5 += q2.y; a6 += q3.x; a7 += q3.y; }
                    ACC(u0); ACC(u1); ACC(u2); ACC(u3);
                    ACC(u4); ACC(u5); ACC(u6); ACC(u7);
#undef ACC
                    i0 = j0; i1 = j1;
                }
            }
            o.x = pack_half2(a0, a1);
            o.y = pack_half2(a2, a3);
            o.z = pack_half2(a4, a5);
            o.w = pack_half2(a6, a7);
        }
        ((uint4*)sZ)[(size_t)nl_ * TPN + c] = o;
    }
    __syncthreads();

    // ---- Phase B: WMMA MLP ----
    int wid = t >> 5, lane = t & 31;
    float* myscr = scr + wid * 256;

    wmma::fragment<wmma::matrix_a, 16, 16, 16, __half, wmma::row_major> fa;
    wmma::fragment<wmma::matrix_b, 16, 16, 16, __half, wmma::row_major> fb;
    wmma::fragment<wmma::accumulator, 16, 16, 16, float> fc;

    for (int job = wid; job < 28; job += 16) {
        int mt = job & 3;
        int nt = job >> 2;
        wmma::fill_fragment(fc, 0.0f);
#pragma unroll
        for (int kk = 0; kk < 4; kk++) {
            wmma::load_matrix_sync(fa, sZ + (mt * 16) * 64 + kk * 16, 64);
            wmma::load_matrix_sync(fb, sW1 + (kk * 16) * 112 + nt * 16, 112);
            wmma::mma_sync(fc, fa, fb, fc);
        }
        wmma::store_matrix_sync(myscr, fc, 16, wmma::mem_row_major);
        __syncwarp();
        for (int e = lane; e < 256; e += 32) {
            int r = e >> 4, cc = e & 15;
            int gc = nt * 16 + cc;
            float v = fmaxf(myscr[e] + sB1[gc], 0.0f);
            sY[(mt * 16 + r) * 112 + gc] = __float2half(v);
        }
        __syncwarp();
    }
    __syncthreads();

    __half* hout = g_h[l];
    for (int job = wid; job < 16; job += 16) {
        int mt = job & 3;
        int nt = job >> 2;
        wmma::fill_fragment(fc, 0.0f);
#pragma unroll
        for (int kk = 0; kk < 7; kk++) {
            wmma::load_matrix_sync(fa, sY + (mt * 16) * 112 + kk * 16, 112);
            wmma::load_matrix_sync(fb, sW2 + (kk * 16) * 64 + nt * 16, 64);
            wmma::mma_sync(fc, fa, fb, fc);
        }
        wmma::store_matrix_sync(myscr, fc, 16, wmma::mem_row_major);
        __syncwarp();
        for (int e = lane; e < 256; e += 32) {
            int r = e >> 4, cc = e & 15;
            int gr = node0 + mt * 16 + r;
            int gc = nt * 16 + cc;
            if (gc < HID && gr < n) {
                float v = fmaxf(myscr[e] + sB2[gc], 0.0f);
                hout[(size_t)gr * ROWH + gc] = __float2half(v);
            }
        }
        __syncwarp();
    }
}

// ---------------------------------------------------------------------------
// WMMA final; prologue re-zeroes g_deg for the next call (deterministic).
// ---------------------------------------------------------------------------
#define FIN_SMEM 61696

__global__ void __launch_bounds__(256) final_wmma_kernel(
        const float* __restrict__ lb, float* __restrict__ out, int n)
{
    extern __shared__ __align__(16) char smem[];
    __half* sH  = (__half*)(smem);
    __half* sW  = (__half*)(smem + 26624);
    float*  scr = (float*)(smem + 53248);
    float*  sLB = (float*)(smem + 61440);

    int t = threadIdx.x;
    int node0 = blockIdx.x * 64;

    // re-zero degree counters for the next kernel_launch call
    {
        int g = blockIdx.x * blockDim.x + t;
        if (g < n) g_deg[g] = 0;
    }

    {
        int node = t & 63, seg = t >> 6;
        const __half* src = ((seg == 0) ? g_hin : g_h[seg - 1])
                            + (size_t)(node0 + node) * ROWH;
        const uint2* s2 = (const uint2*)src;
        uint2* d2 = (uint2*)(sH + node * 208 + seg * HID);
#pragma unroll
        for (int i = 0; i < 13; i++) d2[i] = __ldg(&s2[i]);
    }
    for (int i = t; i < 1664; i += 256)
        ((uint4*)sW)[i] = __ldg(&((const uint4*)g_lwh)[i]);
    if (t < 64) sLB[t] = (t < HID) ? __ldg(&lb[t]) : 0.f;
    __syncthreads();

    int wid = t >> 5, lane = t & 31;
    float* myscr = scr + wid * 256;

    wmma::fragment<wmma::matrix_a, 16, 16, 16, __half, wmma::row_major> fa;
    wmma::fragment<wmma::matrix_b, 16, 16, 16, __half, wmma::row_major> fb;
    wmma::fragment<wmma::accumulator, 16, 16, 16, float> fc;

    for (int job = wid; job < 16; job += 8) {
        int mt = job & 3;
        int nt = job >> 2;
        wmma::fill_fragment(fc, 0.0f);
#pragma unroll
        for (int kk = 0; kk < 13; kk++) {
            wmma::load_matrix_sync(fa, sH + (mt * 16) * 208 + kk * 16, 208);
            wmma::load_matrix_sync(fb, sW + (kk * 16) * 64 + nt * 16, 64);
            wmma::mma_sync(fc, fa, fb, fc);
        }
        wmma::store_matrix_sync(myscr, fc, 16, wmma::mem_row_major);
        __syncwarp();
        for (int e = lane; e < 256; e += 32) {
            int r = e >> 4, cc = e & 15;
            int gr = node0 + mt * 16 + r;
            int gc = nt * 16 + cc;
            if (gc < HID && gr < n)
                out[(size_t)gr * HID + gc] = myscr[e] + sLB[gc];
        }
        __syncwarp();
    }
}

// ---------------------------------------------------------------------------
extern "C" void kernel_launch(void* const* d_in, const int* in_sizes, int n_in,
                              void* d_out, int out_size)
{
    const float* x    = (const float*)d_in[0];
    const int*   ei   = (const int*)  d_in[1];
    const float* w1   = (const float*)d_in[2];
    const float* b1   = (const float*)d_in[3];
    const float* w2   = (const float*)d_in[4];
    const float* b2   = (const float*)d_in[5];
    const float* eps  = (const float*)d_in[6];
    const float* lw   = (const float*)d_in[7];
    const float* lb   = (const float*)d_in[8];
    float* out = (float*)d_out;

    int n = in_sizes[0] / HID;
    int E = in_sizes[1] / 2;

    cudaFuncSetAttribute(layer_fused_kernel,
                         cudaFuncAttributeMaxDynamicSharedMemorySize, FUSE_SMEM);
    cudaFuncSetAttribute(final_wmma_kernel,
                         cudaFuncAttributeMaxDynamicSharedMemorySize, FIN_SMEM);

    int prepT  = (n + 1) * TPN;
    int placeT = (E >> 3) + (E & 7);
    int wT     = NL * HID * HID2 * 2 + 4 * HID * HID;
    int buildBlocks = (prepT + placeT + wT + 255) / 256;
    int tcBlocks    = (n + 63) / 64;

    build_kernel<<<buildBlocks, 256>>>(x, ei, w1, w2, lw, n, E);

    for (int l = 0; l < NL; l++)
        layer_fused_kernel<<<tcBlocks, 512, FUSE_SMEM>>>(eps, b1, b2, l, n);

    final_wmma_kernel<<<tcBlocks, 256, FIN_SMEM>>>(lb, out, n);
}